// round 13
// baseline (speedup 1.0000x reference)
#include <cuda_runtime.h>
#include <cstdint>
#include <math.h>

typedef unsigned long long ull;

#define SEQ   2048
#define DM    1024
#define NH    16
#define DH    128
#define HD    2048   // NH*DH

// ---------------- scratch ----------------
__device__ float g_Q[NH * SEQ * DH];   // compacted masked rows, head-major
__device__ float g_K[NH * SEQ * DH];
__device__ float g_V[NH * SEQ * DH];
__device__ float g_xpart[8][DM];
__device__ float g_xmean[DM];
__device__ float g_vpart[4][HD];
__device__ float g_vmean[HD];
__device__ int   g_mask[SEQ];
__device__ int   g_midx[SEQ];
__device__ int   g_kbest[NH * SEQ];
__device__ int   g_mcount;
__device__ int   g_mcount64;
__device__ int   g_ticket;

// ---------------- f32x2 helpers ----------------
__device__ __forceinline__ void fma2(ull& d, ull a, ull b) {
    asm("fma.rn.f32x2 %0, %1, %2, %0;" : "+l"(d) : "l"(a), "l"(b));
}
__device__ __forceinline__ ull packf2(float lo, float hi) {
    ull r; asm("mov.b64 %0, {%1, %2};" : "=l"(r) : "f"(lo), "f"(hi)); return r;
}
__device__ __forceinline__ ull add2(ull a, ull b) {
    ull r; asm("add.rn.f32x2 %0, %1, %2;" : "=l"(r) : "l"(a), "l"(b)); return r;
}
__device__ __forceinline__ float f2sum(ull v) {
    float lo, hi; asm("mov.b64 {%0, %1}, %2;" : "=f"(lo), "=f"(hi) : "l"(v));
    return lo + hi;
}
__device__ __forceinline__ void cp16(unsigned dst, const void* src) {
    asm volatile("cp.async.cg.shared.global [%0], [%1], 16;" :: "r"(dst), "l"(src) : "memory");
}
__device__ __forceinline__ void cp_commit() {
    asm volatile("cp.async.commit_group;" ::: "memory");
}
__device__ __forceinline__ void cp_wait0() {
    asm volatile("cp.async.wait_group 0;" ::: "memory");
}

// ---------------- mask decode + compaction (+ ticket reset) ----------------
__global__ void mask_setup_kernel(const unsigned char* __restrict__ p)
{
    __shared__ int sm[SEQ];
    __shared__ int cnt[64];
    __shared__ int base[65];
    __shared__ int not_i32, not_f32;
    int t = threadIdx.x;               // 1024 threads
    if (t == 0) { not_i32 = 0; not_f32 = 0; g_ticket = 0; }
    __syncthreads();
    if (t < 512) {
        unsigned w = ((const unsigned*)p)[t];
        if (!(w == 0u || w == 1u))          atomicExch(&not_i32, 1);
        if (!(w == 0u || w == 0x3F800000u)) atomicExch(&not_f32, 1);
    }
    __syncthreads();
    int cls = (!not_i32) ? 0 : ((!not_f32) ? 1 : 2);
    for (int i = t; i < SEQ; i += 1024) {
        int v;
        if (cls == 0)      v = (((const int*)p)[i]   != 0);
        else if (cls == 1) v = (((const float*)p)[i] != 0.0f);
        else               v = (p[i] != 0);
        sm[i] = v; g_mask[i] = v;
    }
    __syncthreads();
    if (t < 64) {
        int c = 0;
        for (int i = 0; i < 32; i++) c += sm[t * 32 + i];
        cnt[t] = c;
    }
    __syncthreads();
    if (t == 0) {
        int acc = 0;
        for (int c = 0; c < 64; c++) { base[c] = acc; acc += cnt[c]; }
        base[64] = acc;
        g_mcount = acc;
        g_mcount64 = (acc + 63) & ~63;
    }
    __syncthreads();
    if (t < 64) {
        int pos = base[t];
        for (int i = 0; i < 32; i++)
            if (sm[t * 32 + i]) g_midx[pos++] = t * 32 + i;
    }
    __syncthreads();
    int mc = base[64];
    for (int i = t; i < SEQ; i += 1024)
        if (i >= mc) g_midx[i] = 0;
}

// ---------------- pipelined proj tile: 64(m) x 128(n), k-step 32, 4x4 micro ----------------
// dsm (ull): Xd[64][33] @0 (2112), Wp0[32][66] @2112 (2112), Wp1 @4224 (2112),
//            ridx @6336 (64 int).  bytes = 6336*8 + 256 = 50944
#define PROJ_SMEM_BYTES (6336 * 8 + 256)

__device__ __forceinline__ void proj_tile(
    const float* __restrict__ X, const float* __restrict__ W,
    const float* __restrict__ bias, float* __restrict__ out,
    int m0, int n0, ull* dsm)
{
    ull* Xd   = dsm;            // [64][33]
    ull* Wp0  = dsm + 2112;     // [32][66]
    ull* Wp1  = dsm + 4224;     // [32][66]
    int* ridx = (int*)(dsm + 6336);

    const int t  = threadIdx.x;
    const int tx = t & 15, ty = t >> 4;

    if (t < 64) ridx[t] = g_midx[m0 + t];
    __syncthreads();

    // per-thread X gather rows: r = (t>>5) + 8u, col kk = t&31
    const int kkx = t & 31;
    const int rb  = t >> 5;
    int xrow[8];
    #pragma unroll
    for (int u = 0; u < 8; u++) xrow[u] = ridx[rb + 8 * u];

    const unsigned wb0 = (unsigned)__cvta_generic_to_shared(Wp0);
    const unsigned wb1 = (unsigned)__cvta_generic_to_shared(Wp1);

    // ---- prologue: W(k0=0) -> buf0, X(0) -> regs ----
    #pragma unroll
    for (int u = 0; u < 4; u++) {
        int c = t + 256 * u;
        int kk = c >> 5, c16 = c & 31;
        cp16(wb0 + (unsigned)(kk * 66 + c16 * 2) * 8,
             W + (size_t)kk * HD + n0 + c16 * 4);
    }
    cp_commit();
    float xr[8];
    #pragma unroll
    for (int u = 0; u < 8; u++) xr[u] = X[(size_t)xrow[u] * DM + kkx];
    cp_wait0();
    #pragma unroll
    for (int u = 0; u < 8; u++) Xd[(rb + 8 * u) * 33 + kkx] = packf2(xr[u], xr[u]);
    __syncthreads();

    ull acc[4][4];
    #pragma unroll
    for (int i = 0; i < 4; i++)
        #pragma unroll
        for (int j = 0; j < 4; j++) acc[i][j] = 0ull;

    const int r0 = ty << 2;
    int cur = 0;

    for (int k0 = 0; k0 < DM; k0 += 32) {
        const bool more = (k0 + 32 < DM);
        if (more) {
            unsigned wb = cur ? wb0 : wb1;   // fill alternate buffer
            #pragma unroll
            for (int u = 0; u < 4; u++) {
                int c = t + 256 * u;
                int kk = c >> 5, c16 = c & 31;
                cp16(wb + (unsigned)(kk * 66 + c16 * 2) * 8,
                     W + (size_t)(k0 + 32 + kk) * HD + n0 + c16 * 4);
            }
            cp_commit();
            #pragma unroll
            for (int u = 0; u < 8; u++)
                xr[u] = X[(size_t)xrow[u] * DM + (k0 + 32) + kkx];
        }
        const ull* Wc = cur ? Wp1 : Wp0;
        #pragma unroll 4
        for (int kk = 0; kk < 32; kk++) {
            ull a0 = Xd[(r0 + 0) * 33 + kk];
            ull a1 = Xd[(r0 + 1) * 33 + kk];
            ull a2 = Xd[(r0 + 2) * 33 + kk];
            ull a3 = Xd[(r0 + 3) * 33 + kk];
            const ull* wr = Wc + kk * 66 + tx;
            #pragma unroll
            for (int j = 0; j < 4; j++) {
                ull b = wr[16 * j];
                fma2(acc[0][j], a0, b);
                fma2(acc[1][j], a1, b);
                fma2(acc[2][j], a2, b);
                fma2(acc[3][j], a3, b);
            }
        }
        __syncthreads();            // compute done; Xd reusable, W buf consumed
        if (more) {
            #pragma unroll
            for (int u = 0; u < 8; u++)
                Xd[(rb + 8 * u) * 33 + kkx] = packf2(xr[u], xr[u]);
            cp_wait0();             // alternate W buffer landed
        }
        __syncthreads();
        cur ^= 1;
    }

    const int h = n0 >> 7;                 // n-tile spans exactly one head
    #pragma unroll
    for (int j = 0; j < 4; j++) {
        int cp = tx + 16 * j;
        int d  = 2 * cp;
        ull bpair = *(const ull*)(bias + n0 + d);
        #pragma unroll
        for (int i = 0; i < 4; i++) {
            ull* dst = (ull*)(out + (size_t)(h * SEQ + m0 + r0 + i) * DH + d);
            *dst = add2(acc[i][j], bpair);
        }
    }
}

// ---------------- persistent projection kernel: ticket-scheduled tiles ----------------
__global__ __launch_bounds__(256, 2) void proj_kernel(
    const float* __restrict__ X,
    const float* __restrict__ Wq, const float* __restrict__ bq,
    const float* __restrict__ Wk, const float* __restrict__ bk,
    const float* __restrict__ Wv, const float* __restrict__ bv)
{
    extern __shared__ __align__(16) ull dsm[];
    __shared__ int s_id;
    const int nmt   = g_mcount64 >> 6;   // active m-tiles
    const int nper  = nmt * 16;          // tiles per matrix
    const int total = nper * 3;

    for (;;) {
        __syncthreads();                 // protect s_id and smem reuse
        if (threadIdx.x == 0) s_id = atomicAdd(&g_ticket, 1);
        __syncthreads();
        const int id = s_id;
        if (id >= total) break;

        const int mat   = id / nper;
        const int local = id - mat * nper;
        const int mt = local >> 4, nt = local & 15;

        const float *W, *bias; float* out;
        if (mat == 0)      { W = Wq; bias = bq; out = g_Q; }
        else if (mat == 1) { W = Wk; bias = bk; out = g_K; }
        else               { W = Wv; bias = bv; out = g_V; }

        proj_tile(X, W, bias, out, mt << 6, nt << 7, dsm);
    }
}

// ---------------- score kernel: 64q x 64k tiles, register argmin + shfl ----------------
// sm floats: Qs[64][128] @0 (8192), Ks[64][130] @8192 (8320) -> 16512 floats
#define SC_SMEM_BYTES (16512 * 4)

__global__ __launch_bounds__(256, 2) void score_kernel(void)
{
    extern __shared__ __align__(16) float sm[];
    float* Qs = sm;            // stride 128 (a-loads are broadcast)
    float* Ks = sm + 8192;     // stride 130 (b-loads conflict-free)

    const int t  = threadIdx.x;
    const int tx = t & 15, ty = t >> 4;
    const int h  = blockIdx.y;
    const int q0 = blockIdx.x << 6;
    const int mc = g_mcount;
    if (q0 >= mc) return;

    const float* Qg = g_Q + (size_t)(h * SEQ + q0) * DH;
    #pragma unroll
    for (int u = 0; u < 8; u++) {
        int i = t + u * 256;
        float4 v = ((const float4*)Qg)[i];
        int r = i >> 5, dd = (i & 31) << 2;
        ull* p = (ull*)&Qs[r * 128 + dd];
        p[0] = packf2(v.x, v.y); p[1] = packf2(v.z, v.w);
    }

    float bv_[4]; int bi_[4];
    #pragma unroll
    for (int i = 0; i < 4; i++) { bv_[i] = INFINITY; bi_[i] = 0; }

    const int r0 = ty << 2;
    const int nkt = g_mcount64 >> 6;
    for (int kt = 0; kt < nkt; kt++) {
        const int k0 = kt << 6;
        __syncthreads();               // Q fill / prior reads done
        const float* Kg = g_K + (size_t)(h * SEQ + k0) * DH;
        #pragma unroll
        for (int u = 0; u < 8; u++) {
            int i = t + u * 256;
            float4 v = ((const float4*)Kg)[i];
            int r = i >> 5, dd = (i & 31) << 2;
            ull* p = (ull*)&Ks[r * 130 + dd];
            p[0] = packf2(v.x, v.y); p[1] = packf2(v.z, v.w);
        }
        __syncthreads();

        ull acc[4][4];
        #pragma unroll
        for (int i = 0; i < 4; i++)
            #pragma unroll
            for (int j = 0; j < 4; j++) acc[i][j] = 0ull;

        #pragma unroll 4
        for (int dp = 0; dp < 64; dp++) {
            ull a0 = *(const ull*)&Qs[(r0 + 0) * 128 + 2 * dp];
            ull a1 = *(const ull*)&Qs[(r0 + 1) * 128 + 2 * dp];
            ull a2 = *(const ull*)&Qs[(r0 + 2) * 128 + 2 * dp];
            ull a3 = *(const ull*)&Qs[(r0 + 3) * 128 + 2 * dp];
            #pragma unroll
            for (int j = 0; j < 4; j++) {
                ull b = *(const ull*)&Ks[(tx + 16 * j) * 130 + 2 * dp];
                fma2(acc[0][j], a0, b);
                fma2(acc[1][j], a1, b);
                fma2(acc[2][j], a2, b);
                fma2(acc[3][j], a3, b);
            }
        }
        #pragma unroll
        for (int i = 0; i < 4; i++) {
            #pragma unroll
            for (int j = 0; j < 4; j++) {
                int c = k0 + tx + 16 * j;
                float s = f2sum(acc[i][j]);
                if (c < mc && s < bv_[i]) { bv_[i] = s; bi_[i] = c; }
            }
        }
    }
    // half-warp shuffle argmin (row r0+i owned by 16 lanes with same ty)
    #pragma unroll
    for (int i = 0; i < 4; i++) {
        #pragma unroll
        for (int off = 8; off >= 1; off >>= 1) {
            float ov = __shfl_xor_sync(0xffffffffu, bv_[i], off);
            int   oi = __shfl_xor_sync(0xffffffffu, bi_[i], off);
            if (ov < bv_[i]) { bv_[i] = ov; bi_[i] = oi; }
        }
    }
    if (tx == 0) {
        #pragma unroll
        for (int i = 0; i < 4; i++) {
            int row = q0 + r0 + i;
            if (row < mc) g_kbest[h * SEQ + g_midx[row]] = bi_[i];
        }
    }
}

// ---------------- mean(X) and mean-V via linearity ----------------
__global__ void xpart_kernel(const float* __restrict__ X)
{
    int j  = blockIdx.x * 256 + threadIdx.x;   // grid.x = 4
    int rb = blockIdx.y;                        // 8
    const float* p = X + (size_t)rb * 256 * DM + j;
    float s = 0.0f;
    #pragma unroll 8
    for (int r = 0; r < 256; r++) s += p[(size_t)r * DM];
    g_xpart[rb][j] = s;
}
__global__ void xmean_kernel(void)
{
    int j = blockIdx.x * 256 + threadIdx.x;    // grid 4
    float s = 0.0f;
    #pragma unroll
    for (int rb = 0; rb < 8; rb++) s += g_xpart[rb][j];
    g_xmean[j] = s * (1.0f / 2048.0f);
}
__global__ void vgemv_kernel(const float* __restrict__ Wv)
{
    __shared__ float xm[256];
    int t = threadIdx.x;
    int part = blockIdx.y;                     // 4 k-slices of 256
    xm[t] = g_xmean[part * 256 + t];
    __syncthreads();
    int c = blockIdx.x * 256 + t;              // grid.x 8
    float a0 = 0, a1 = 0, a2 = 0, a3 = 0;
    const float* Wp = Wv + (size_t)part * 256 * HD + c;
    for (int j = 0; j < 256; j += 4) {
        a0 += xm[j + 0] * Wp[(size_t)(j + 0) * HD];
        a1 += xm[j + 1] * Wp[(size_t)(j + 1) * HD];
        a2 += xm[j + 2] * Wp[(size_t)(j + 2) * HD];
        a3 += xm[j + 3] * Wp[(size_t)(j + 3) * HD];
    }
    g_vpart[part][c] = (a0 + a1) + (a2 + a3);
}
__global__ void vcombine_kernel(const float* __restrict__ bv)
{
    int c = blockIdx.x * 256 + threadIdx.x;    // grid 8
    g_vmean[c] = ((g_vpart[0][c] + g_vpart[1][c]) + (g_vpart[2][c] + g_vpart[3][c])) + bv[c];
}

// ---------------- output assembly ----------------
__global__ void assemble_kernel(float* __restrict__ out)
{
    int s = blockIdx.x;
    int t = threadIdx.x;               // 256
    if (g_mask[s]) {
        #pragma unroll
        for (int i = 0; i < 8; i++) {
            int idx = i * 256 + t;
            int h = idx >> 7, d = idx & 127;
            int kb = g_kbest[h * SEQ + s];
            out[(size_t)s * HD + idx] = g_V[(size_t)(h * SEQ + kb) * DH + d];
        }
    } else {
        #pragma unroll
        for (int i = 0; i < 8; i++) {
            int idx = i * 256 + t;
            out[(size_t)s * HD + idx] = g_vmean[idx];
        }
    }
}

// ---------------- launch ----------------
extern "C" void kernel_launch(void* const* d_in, const int* in_sizes, int n_in,
                              void* d_out, int out_size)
{
    const float* X          = (const float*)d_in[0];
    const unsigned char* mp = (const unsigned char*)d_in[1];
    const float* Wq = (const float*)d_in[2];
    const float* bq = (const float*)d_in[3];
    const float* Wk = (const float*)d_in[4];
    const float* bk = (const float*)d_in[5];
    const float* Wv = (const float*)d_in[6];
    const float* bv = (const float*)d_in[7];
    float* out = (float*)d_out;

    mask_setup_kernel<<<1, 1024>>>(mp);

    xpart_kernel<<<dim3(4, 8), 256>>>(X);
    xmean_kernel<<<4, 256>>>();

    cudaFuncSetAttribute(proj_kernel, cudaFuncAttributeMaxDynamicSharedMemorySize, PROJ_SMEM_BYTES);
    proj_kernel<<<296, 256, PROJ_SMEM_BYTES>>>(X, Wq, bq, Wk, bk, Wv, bv);

    vgemv_kernel<<<dim3(8, 4), 256>>>(Wv);
    vcombine_kernel<<<8, 256>>>(bv);

    cudaFuncSetAttribute(score_kernel, cudaFuncAttributeMaxDynamicSharedMemorySize, SC_SMEM_BYTES);
    score_kernel<<<dim3(SEQ / 64, NH), 256, SC_SMEM_BYTES>>>();

    assemble_kernel<<<SEQ, 256>>>(out);
}

// round 14
// speedup vs baseline: 1.0279x; 1.0279x over previous
#include <cuda_runtime.h>
#include <cstdint>
#include <math.h>

typedef unsigned long long ull;

#define SEQ   2048
#define DM    1024
#define NH    16
#define DH    128
#define HD    2048   // NH*DH

// ---------------- scratch ----------------
__device__ float g_Q[NH * SEQ * DH];   // compacted masked rows, head-major
__device__ float g_K[NH * SEQ * DH];
__device__ float g_V[NH * SEQ * DH];
__device__ float g_xpart[8][DM];
__device__ float g_xmean[DM];
__device__ float g_vpart[4][HD];
__device__ float g_vmean[HD];
__device__ int   g_mask[SEQ];
__device__ int   g_midx[SEQ];
__device__ int   g_kbest[NH * SEQ];
__device__ int   g_mcount;
__device__ int   g_mcount64;

// ---------------- f32x2 / cp.async helpers ----------------
__device__ __forceinline__ void fma2(ull& d, ull a, ull b) {
    asm("fma.rn.f32x2 %0, %1, %2, %0;" : "+l"(d) : "l"(a), "l"(b));
}
__device__ __forceinline__ ull packf2(float lo, float hi) {
    ull r; asm("mov.b64 %0, {%1, %2};" : "=l"(r) : "f"(lo), "f"(hi)); return r;
}
__device__ __forceinline__ ull add2(ull a, ull b) {
    ull r; asm("add.rn.f32x2 %0, %1, %2;" : "=l"(r) : "l"(a), "l"(b)); return r;
}
__device__ __forceinline__ float f2sum(ull v) {
    float lo, hi; asm("mov.b64 {%0, %1}, %2;" : "=f"(lo), "=f"(hi) : "l"(v));
    return lo + hi;
}
__device__ __forceinline__ void cp16(unsigned dst, const void* src) {
    asm volatile("cp.async.cg.shared.global [%0], [%1], 16;" :: "r"(dst), "l"(src) : "memory");
}
__device__ __forceinline__ void cp8(unsigned dst, const void* src) {
    asm volatile("cp.async.ca.shared.global [%0], [%1], 8;" :: "r"(dst), "l"(src) : "memory");
}
__device__ __forceinline__ void cp_commit() {
    asm volatile("cp.async.commit_group;" ::: "memory");
}
__device__ __forceinline__ void cp_wait0() {
    asm volatile("cp.async.wait_group 0;" ::: "memory");
}

// ---------------- mask decode + compaction ----------------
__global__ void mask_setup_kernel(const unsigned char* __restrict__ p)
{
    __shared__ int sm[SEQ];
    __shared__ int cnt[64];
    __shared__ int base[65];
    __shared__ int not_i32, not_f32;
    int t = threadIdx.x;               // 1024 threads
    if (t == 0) { not_i32 = 0; not_f32 = 0; }
    __syncthreads();
    if (t < 512) {
        unsigned w = ((const unsigned*)p)[t];
        if (!(w == 0u || w == 1u))          atomicExch(&not_i32, 1);
        if (!(w == 0u || w == 0x3F800000u)) atomicExch(&not_f32, 1);
    }
    __syncthreads();
    int cls = (!not_i32) ? 0 : ((!not_f32) ? 1 : 2);
    for (int i = t; i < SEQ; i += 1024) {
        int v;
        if (cls == 0)      v = (((const int*)p)[i]   != 0);
        else if (cls == 1) v = (((const float*)p)[i] != 0.0f);
        else               v = (p[i] != 0);
        sm[i] = v; g_mask[i] = v;
    }
    __syncthreads();
    if (t < 64) {
        int c = 0;
        for (int i = 0; i < 32; i++) c += sm[t * 32 + i];
        cnt[t] = c;
    }
    __syncthreads();
    if (t == 0) {
        int acc = 0;
        for (int c = 0; c < 64; c++) { base[c] = acc; acc += cnt[c]; }
        base[64] = acc;
        g_mcount = acc;
        g_mcount64 = (acc + 63) & ~63;
    }
    __syncthreads();
    if (t < 64) {
        int pos = base[t];
        for (int i = 0; i < 32; i++)
            if (sm[t * 32 + i]) g_midx[pos++] = t * 32 + i;
    }
    __syncthreads();
    int mc = base[64];
    for (int i = t; i < SEQ; i += 1024)
        if (i >= mc) g_midx[i] = 0;
}

// ---------------- pipelined proj: 64(m) x 128(n), k-step 32, 4x4 micro (R11) ----------------
// dsm (ull): Xd[64][33] @0 (2112), Wp0[32][66] @2112 (2112), Wp1 @4224 (2112),
//            ridx @6336 (64 int).  bytes = 6336*8 + 256 = 50944
#define PROJ_SMEM_BYTES (6336 * 8 + 256)

__global__ __launch_bounds__(256, 2) void proj_kernel(
    const float* __restrict__ X,
    const float* __restrict__ Wq, const float* __restrict__ bq,
    const float* __restrict__ Wk, const float* __restrict__ bk,
    const float* __restrict__ Wv, const float* __restrict__ bv)
{
    extern __shared__ __align__(16) ull dsm[];
    ull* Xd   = dsm;            // [64][33]
    ull* Wp0  = dsm + 2112;     // [32][66]
    ull* Wp1  = dsm + 4224;     // [32][66]
    int* ridx = (int*)(dsm + 6336);

    const int t  = threadIdx.x;
    const int tx = t & 15, ty = t >> 4;
    const int m0 = blockIdx.y << 6;
    if (m0 >= g_mcount64) return;
    const int n0 = blockIdx.x << 7;

    const float *W, *bias; float* out;
    if (blockIdx.z == 0)      { W = Wq; bias = bq; out = g_Q; }
    else if (blockIdx.z == 1) { W = Wk; bias = bk; out = g_K; }
    else                      { W = Wv; bias = bv; out = g_V; }

    if (t < 64) ridx[t] = g_midx[m0 + t];
    __syncthreads();

    // per-thread X gather rows: r = (t>>5) + 8u, col kk = t&31
    const int kkx = t & 31;
    const int rb  = t >> 5;
    int xrow[8];
    #pragma unroll
    for (int u = 0; u < 8; u++) xrow[u] = ridx[rb + 8 * u];

    const unsigned wb0 = (unsigned)__cvta_generic_to_shared(Wp0);
    const unsigned wb1 = (unsigned)__cvta_generic_to_shared(Wp1);

    // ---- prologue: W(k0=0) -> buf0, X(0) -> regs ----
    #pragma unroll
    for (int u = 0; u < 4; u++) {
        int c = t + 256 * u;
        int kk = c >> 5, c16 = c & 31;
        cp16(wb0 + (unsigned)(kk * 66 + c16 * 2) * 8,
             W + (size_t)kk * HD + n0 + c16 * 4);
    }
    cp_commit();
    float xr[8];
    #pragma unroll
    for (int u = 0; u < 8; u++) xr[u] = X[(size_t)xrow[u] * DM + kkx];
    cp_wait0();
    #pragma unroll
    for (int u = 0; u < 8; u++) Xd[(rb + 8 * u) * 33 + kkx] = packf2(xr[u], xr[u]);
    __syncthreads();

    ull acc[4][4];
    #pragma unroll
    for (int i = 0; i < 4; i++)
        #pragma unroll
        for (int j = 0; j < 4; j++) acc[i][j] = 0ull;

    const int r0 = ty << 2;
    int cur = 0;

    for (int k0 = 0; k0 < DM; k0 += 32) {
        const bool more = (k0 + 32 < DM);
        if (more) {
            unsigned wb = cur ? wb0 : wb1;   // fill alternate buffer
            #pragma unroll
            for (int u = 0; u < 4; u++) {
                int c = t + 256 * u;
                int kk = c >> 5, c16 = c & 31;
                cp16(wb + (unsigned)(kk * 66 + c16 * 2) * 8,
                     W + (size_t)(k0 + 32 + kk) * HD + n0 + c16 * 4);
            }
            cp_commit();
            #pragma unroll
            for (int u = 0; u < 8; u++)
                xr[u] = X[(size_t)xrow[u] * DM + (k0 + 32) + kkx];
        }
        const ull* Wc = cur ? Wp1 : Wp0;
        #pragma unroll 4
        for (int kk = 0; kk < 32; kk++) {
            ull a0 = Xd[(r0 + 0) * 33 + kk];
            ull a1 = Xd[(r0 + 1) * 33 + kk];
            ull a2 = Xd[(r0 + 2) * 33 + kk];
            ull a3 = Xd[(r0 + 3) * 33 + kk];
            const ull* wr = Wc + kk * 66 + tx;
            #pragma unroll
            for (int j = 0; j < 4; j++) {
                ull b = wr[16 * j];
                fma2(acc[0][j], a0, b);
                fma2(acc[1][j], a1, b);
                fma2(acc[2][j], a2, b);
                fma2(acc[3][j], a3, b);
            }
        }
        __syncthreads();            // compute done; Xd reusable, W buf consumed
        if (more) {
            #pragma unroll
            for (int u = 0; u < 8; u++)
                Xd[(rb + 8 * u) * 33 + kkx] = packf2(xr[u], xr[u]);
            cp_wait0();             // alternate W buffer landed
        }
        __syncthreads();
        cur ^= 1;
    }

    const int h = n0 >> 7;                 // n-tile spans exactly one head
    #pragma unroll
    for (int j = 0; j < 4; j++) {
        int cp = tx + 16 * j;
        int d  = 2 * cp;
        ull bpair = *(const ull*)(bias + n0 + d);
        #pragma unroll
        for (int i = 0; i < 4; i++) {
            ull* dst = (ull*)(out + (size_t)(h * SEQ + m0 + r0 + i) * DH + d);
            *dst = add2(acc[i][j], bpair);
        }
    }
}

// ---------------- score kernel: 64q x 64k tiles, cp.async K pipeline ----------------
// sm floats: Qs[64][128] @0 (8192), Ks0[64][130] @8192 (8320), Ks1 @16512 (8320)
//   -> 24832 floats = 99328 B  (2 CTAs/SM)
#define SC_SMEM_BYTES (24832 * 4)

__global__ __launch_bounds__(256, 2) void score_kernel(void)
{
    extern __shared__ __align__(16) float sm[];
    float* Qs  = sm;                 // stride 128 (a-loads broadcast)
    float* Ks0 = sm + 8192;          // stride 130 (b-loads conflict-free)
    float* Ks1 = sm + 16512;

    const int t  = threadIdx.x;
    const int tx = t & 15, ty = t >> 4;
    const int h  = blockIdx.y;
    const int q0 = blockIdx.x << 6;
    const int mc = g_mcount;
    if (q0 >= mc) return;

    const unsigned qb  = (unsigned)__cvta_generic_to_shared(Qs);
    const unsigned kb0 = (unsigned)__cvta_generic_to_shared(Ks0);
    const unsigned kb1 = (unsigned)__cvta_generic_to_shared(Ks1);

    // prologue: Q tile (contiguous 32 KB) + K tile 0 via cp.async
    const float* Qg     = g_Q + (size_t)(h * SEQ + q0) * DH;
    const float* KgBase = g_K + (size_t)(h * SEQ) * DH;
    #pragma unroll
    for (int u = 0; u < 8; u++) {
        int c = t + 256 * u;                 // 16B chunk; layout is plain contiguous
        cp16(qb + (unsigned)c * 16, Qg + c * 4);
    }
    #pragma unroll
    for (int u = 0; u < 16; u++) {
        int c = t + 256 * u;                 // 8B chunk: row = c>>6, pair c&63
        int r = c >> 6, c2 = c & 63;
        cp8(kb0 + (unsigned)(r * 130 + c2 * 2) * 4, KgBase + c * 2);
    }
    cp_commit();

    float bv_[4]; int bi_[4];
    #pragma unroll
    for (int i = 0; i < 4; i++) { bv_[i] = INFINITY; bi_[i] = 0; }

    cp_wait0();
    __syncthreads();

    const int r0 = ty << 2;
    const int nkt = g_mcount64 >> 6;
    int cur = 0;

    for (int kt = 0; kt < nkt; kt++) {
        // prefetch next K tile into alternate buffer
        if (kt + 1 < nkt) {
            unsigned kb = cur ? kb0 : kb1;
            const float* Kg = KgBase + (size_t)((kt + 1) << 6) * DH;
            #pragma unroll
            for (int u = 0; u < 16; u++) {
                int c = t + 256 * u;
                int r = c >> 6, c2 = c & 63;
                cp8(kb + (unsigned)(r * 130 + c2 * 2) * 4, Kg + c * 2);
            }
            cp_commit();
        }

        const float* Ks = cur ? Ks1 : Ks0;
        const int k0 = kt << 6;

        ull acc[4][4];
        #pragma unroll
        for (int i = 0; i < 4; i++)
            #pragma unroll
            for (int j = 0; j < 4; j++) acc[i][j] = 0ull;

        #pragma unroll 4
        for (int dp = 0; dp < 64; dp++) {
            ull a0 = *(const ull*)&Qs[(r0 + 0) * 128 + 2 * dp];
            ull a1 = *(const ull*)&Qs[(r0 + 1) * 128 + 2 * dp];
            ull a2 = *(const ull*)&Qs[(r0 + 2) * 128 + 2 * dp];
            ull a3 = *(const ull*)&Qs[(r0 + 3) * 128 + 2 * dp];
            #pragma unroll
            for (int j = 0; j < 4; j++) {
                ull b = *(const ull*)&Ks[(tx + 16 * j) * 130 + 2 * dp];
                fma2(acc[0][j], a0, b);
                fma2(acc[1][j], a1, b);
                fma2(acc[2][j], a2, b);
                fma2(acc[3][j], a3, b);
            }
        }
        #pragma unroll
        for (int i = 0; i < 4; i++) {
            #pragma unroll
            for (int j = 0; j < 4; j++) {
                int c = k0 + tx + 16 * j;
                float s = f2sum(acc[i][j]);
                if (c < mc && s < bv_[i]) { bv_[i] = s; bi_[i] = c; }
            }
        }

        cp_wait0();                // next tile landed
        __syncthreads();           // all threads done with consumed buffer
        cur ^= 1;
    }

    // half-warp shuffle argmin (row r0+i owned by 16 lanes with same ty)
    #pragma unroll
    for (int i = 0; i < 4; i++) {
        #pragma unroll
        for (int off = 8; off >= 1; off >>= 1) {
            float ov = __shfl_xor_sync(0xffffffffu, bv_[i], off);
            int   oi = __shfl_xor_sync(0xffffffffu, bi_[i], off);
            if (ov < bv_[i]) { bv_[i] = ov; bi_[i] = oi; }
        }
    }
    if (tx == 0) {
        #pragma unroll
        for (int i = 0; i < 4; i++) {
            int row = q0 + r0 + i;
            if (row < mc) g_kbest[h * SEQ + g_midx[row]] = bi_[i];
        }
    }
}

// ---------------- mean(X) and mean-V via linearity ----------------
__global__ void xpart_kernel(const float* __restrict__ X)
{
    int j  = blockIdx.x * 256 + threadIdx.x;   // grid.x = 4
    int rb = blockIdx.y;                        // 8
    const float* p = X + (size_t)rb * 256 * DM + j;
    float s = 0.0f;
    #pragma unroll 8
    for (int r = 0; r < 256; r++) s += p[(size_t)r * DM];
    g_xpart[rb][j] = s;
}
__global__ void xmean_kernel(void)
{
    int j = blockIdx.x * 256 + threadIdx.x;    // grid 4
    float s = 0.0f;
    #pragma unroll
    for (int rb = 0; rb < 8; rb++) s += g_xpart[rb][j];
    g_xmean[j] = s * (1.0f / 2048.0f);
}
__global__ void vgemv_kernel(const float* __restrict__ Wv)
{
    __shared__ float xm[256];
    int t = threadIdx.x;
    int part = blockIdx.y;                     // 4 k-slices of 256
    xm[t] = g_xmean[part * 256 + t];
    __syncthreads();
    int c = blockIdx.x * 256 + t;              // grid.x 8
    float a0 = 0, a1 = 0, a2 = 0, a3 = 0;
    const float* Wp = Wv + (size_t)part * 256 * HD + c;
    for (int j = 0; j < 256; j += 4) {
        a0 += xm[j + 0] * Wp[(size_t)(j + 0) * HD];
        a1 += xm[j + 1] * Wp[(size_t)(j + 1) * HD];
        a2 += xm[j + 2] * Wp[(size_t)(j + 2) * HD];
        a3 += xm[j + 3] * Wp[(size_t)(j + 3) * HD];
    }
    g_vpart[part][c] = (a0 + a1) + (a2 + a3);
}
__global__ void vcombine_kernel(const float* __restrict__ bv)
{
    int c = blockIdx.x * 256 + threadIdx.x;    // grid 8
    g_vmean[c] = ((g_vpart[0][c] + g_vpart[1][c]) + (g_vpart[2][c] + g_vpart[3][c])) + bv[c];
}

// ---------------- output assembly ----------------
__global__ void assemble_kernel(float* __restrict__ out)
{
    int s = blockIdx.x;
    int t = threadIdx.x;               // 256
    if (g_mask[s]) {
        #pragma unroll
        for (int i = 0; i < 8; i++) {
            int idx = i * 256 + t;
            int h = idx >> 7, d = idx & 127;
            int kb = g_kbest[h * SEQ + s];
            out[(size_t)s * HD + idx] = g_V[(size_t)(h * SEQ + kb) * DH + d];
        }
    } else {
        #pragma unroll
        for (int i = 0; i < 8; i++) {
            int idx = i * 256 + t;
            out[(size_t)s * HD + idx] = g_vmean[idx];
        }
    }
}

// ---------------- launch ----------------
extern "C" void kernel_launch(void* const* d_in, const int* in_sizes, int n_in,
                              void* d_out, int out_size)
{
    const float* X          = (const float*)d_in[0];
    const unsigned char* mp = (const unsigned char*)d_in[1];
    const float* Wq = (const float*)d_in[2];
    const float* bq = (const float*)d_in[3];
    const float* Wk = (const float*)d_in[4];
    const float* bk = (const float*)d_in[5];
    const float* Wv = (const float*)d_in[6];
    const float* bv = (const float*)d_in[7];
    float* out = (float*)d_out;

    mask_setup_kernel<<<1, 1024>>>(mp);

    xpart_kernel<<<dim3(4, 8), 256>>>(X);
    xmean_kernel<<<4, 256>>>();

    cudaFuncSetAttribute(proj_kernel, cudaFuncAttributeMaxDynamicSharedMemorySize, PROJ_SMEM_BYTES);
    proj_kernel<<<dim3(HD / 128, SEQ / 64, 3), 256, PROJ_SMEM_BYTES>>>(X, Wq, bq, Wk, bk, Wv, bv);

    vgemv_kernel<<<dim3(8, 4), 256>>>(Wv);
    vcombine_kernel<<<8, 256>>>(bv);

    cudaFuncSetAttribute(score_kernel, cudaFuncAttributeMaxDynamicSharedMemorySize, SC_SMEM_BYTES);
    score_kernel<<<dim3(SEQ / 64, NH), 256, SC_SMEM_BYTES>>>();

    assemble_kernel<<<SEQ, 256>>>(out);
}

// round 15
// speedup vs baseline: 1.0527x; 1.0241x over previous
#include <cuda_runtime.h>
#include <cstdint>
#include <math.h>

typedef unsigned long long ull;

#define SEQ   2048
#define DM    1024
#define NH    16
#define DH    128
#define HD    2048   // NH*DH

// ---------------- scratch ----------------
__device__ float g_Q[NH * SEQ * DH];   // compacted masked rows, head-major
__device__ float g_K[NH * SEQ * DH];
__device__ float g_V[NH * SEQ * DH];
__device__ float g_xpart[8][DM];
__device__ float g_xmean[DM];
__device__ float g_vpart[4][HD];
__device__ float g_vmean[HD];
__device__ int   g_mask[SEQ];
__device__ int   g_midx[SEQ];
__device__ int   g_kbest[NH * SEQ];
__device__ int   g_mcount;
__device__ int   g_mcount64;

// ---------------- f32x2 / cp.async helpers ----------------
__device__ __forceinline__ void fma2(ull& d, ull a, ull b) {
    asm("fma.rn.f32x2 %0, %1, %2, %0;" : "+l"(d) : "l"(a), "l"(b));
}
__device__ __forceinline__ ull packf2(float lo, float hi) {
    ull r; asm("mov.b64 %0, {%1, %2};" : "=l"(r) : "f"(lo), "f"(hi)); return r;
}
__device__ __forceinline__ ull add2(ull a, ull b) {
    ull r; asm("add.rn.f32x2 %0, %1, %2;" : "=l"(r) : "l"(a), "l"(b)); return r;
}
__device__ __forceinline__ float f2sum(ull v) {
    float lo, hi; asm("mov.b64 {%0, %1}, %2;" : "=f"(lo), "=f"(hi) : "l"(v));
    return lo + hi;
}
__device__ __forceinline__ void cp16(unsigned dst, const void* src) {
    asm volatile("cp.async.cg.shared.global [%0], [%1], 16;" :: "r"(dst), "l"(src) : "memory");
}
__device__ __forceinline__ void cp8(unsigned dst, const void* src) {
    asm volatile("cp.async.ca.shared.global [%0], [%1], 8;" :: "r"(dst), "l"(src) : "memory");
}
__device__ __forceinline__ void cp_commit() {
    asm volatile("cp.async.commit_group;" ::: "memory");
}
__device__ __forceinline__ void cp_wait0() {
    asm volatile("cp.async.wait_group 0;" ::: "memory");
}

// ---------------- mask decode + compaction ----------------
__global__ void mask_setup_kernel(const unsigned char* __restrict__ p)
{
    __shared__ int sm[SEQ];
    __shared__ int cnt[64];
    __shared__ int base[65];
    __shared__ int not_i32, not_f32;
    int t = threadIdx.x;               // 1024 threads
    if (t == 0) { not_i32 = 0; not_f32 = 0; }
    __syncthreads();
    if (t < 512) {
        unsigned w = ((const unsigned*)p)[t];
        if (!(w == 0u || w == 1u))          atomicExch(&not_i32, 1);
        if (!(w == 0u || w == 0x3F800000u)) atomicExch(&not_f32, 1);
    }
    __syncthreads();
    int cls = (!not_i32) ? 0 : ((!not_f32) ? 1 : 2);
    for (int i = t; i < SEQ; i += 1024) {
        int v;
        if (cls == 0)      v = (((const int*)p)[i]   != 0);
        else if (cls == 1) v = (((const float*)p)[i] != 0.0f);
        else               v = (p[i] != 0);
        sm[i] = v; g_mask[i] = v;
    }
    __syncthreads();
    if (t < 64) {
        int c = 0;
        for (int i = 0; i < 32; i++) c += sm[t * 32 + i];
        cnt[t] = c;
    }
    __syncthreads();
    if (t == 0) {
        int acc = 0;
        for (int c = 0; c < 64; c++) { base[c] = acc; acc += cnt[c]; }
        base[64] = acc;
        g_mcount = acc;
        g_mcount64 = (acc + 63) & ~63;
    }
    __syncthreads();
    if (t < 64) {
        int pos = base[t];
        for (int i = 0; i < 32; i++)
            if (sm[t * 32 + i]) g_midx[pos++] = t * 32 + i;
    }
    __syncthreads();
    int mc = base[64];
    for (int i = t; i < SEQ; i += 1024)
        if (i >= mc) g_midx[i] = 0;
}

// ---------------- pipelined proj: 64(m) x 128(n), k-step 32, 4x4 micro, 3 CTAs/SM ----------------
// dsm (ull): Xd[64][33] @0 (2112), Wp0[32][66] @2112 (2112), Wp1 @4224 (2112),
//            ridx @6336 (64 int).  bytes = 6336*8 + 256 = 50944
#define PROJ_SMEM_BYTES (6336 * 8 + 256)

__global__ __launch_bounds__(256, 3) void proj_kernel(
    const float* __restrict__ X,
    const float* __restrict__ Wq, const float* __restrict__ bq,
    const float* __restrict__ Wk, const float* __restrict__ bk,
    const float* __restrict__ Wv, const float* __restrict__ bv)
{
    extern __shared__ __align__(16) ull dsm[];
    ull* Xd   = dsm;            // [64][33]
    ull* Wp0  = dsm + 2112;     // [32][66]
    ull* Wp1  = dsm + 4224;     // [32][66]
    int* ridx = (int*)(dsm + 6336);

    const int t  = threadIdx.x;
    const int tx = t & 15, ty = t >> 4;
    const int m0 = blockIdx.y << 6;
    if (m0 >= g_mcount64) return;
    const int n0 = blockIdx.x << 7;

    const float *W, *bias; float* out;
    if (blockIdx.z == 0)      { W = Wq; bias = bq; out = g_Q; }
    else if (blockIdx.z == 1) { W = Wk; bias = bk; out = g_K; }
    else                      { W = Wv; bias = bv; out = g_V; }

    if (t < 64) ridx[t] = g_midx[m0 + t];
    __syncthreads();

    // per-thread X gather: rows ridx[rb + 8u] (reloaded from smem each use), col kk = t&31
    const int kkx = t & 31;
    const int rb  = t >> 5;

    const unsigned wb0 = (unsigned)__cvta_generic_to_shared(Wp0);
    const unsigned wb1 = (unsigned)__cvta_generic_to_shared(Wp1);

    // ---- prologue: W(k0=0) -> buf0, X(0) -> regs ----
    #pragma unroll
    for (int u = 0; u < 4; u++) {
        int c = t + 256 * u;
        int kk = c >> 5, c16 = c & 31;
        cp16(wb0 + (unsigned)(kk * 66 + c16 * 2) * 8,
             W + (size_t)kk * HD + n0 + c16 * 4);
    }
    cp_commit();
    float xr[8];
    #pragma unroll
    for (int u = 0; u < 8; u++) xr[u] = X[(size_t)ridx[rb + 8 * u] * DM + kkx];
    cp_wait0();
    #pragma unroll
    for (int u = 0; u < 8; u++) Xd[(rb + 8 * u) * 33 + kkx] = packf2(xr[u], xr[u]);
    __syncthreads();

    ull acc[4][4];
    #pragma unroll
    for (int i = 0; i < 4; i++)
        #pragma unroll
        for (int j = 0; j < 4; j++) acc[i][j] = 0ull;

    const int r0 = ty << 2;
    int cur = 0;

    for (int k0 = 0; k0 < DM; k0 += 32) {
        const bool more = (k0 + 32 < DM);
        if (more) {
            unsigned wb = cur ? wb0 : wb1;   // fill alternate buffer
            #pragma unroll
            for (int u = 0; u < 4; u++) {
                int c = t + 256 * u;
                int kk = c >> 5, c16 = c & 31;
                cp16(wb + (unsigned)(kk * 66 + c16 * 2) * 8,
                     W + (size_t)(k0 + 32 + kk) * HD + n0 + c16 * 4);
            }
            cp_commit();
            #pragma unroll
            for (int u = 0; u < 8; u++)
                xr[u] = X[(size_t)ridx[rb + 8 * u] * DM + (k0 + 32) + kkx];
        }
        const ull* Wc = cur ? Wp1 : Wp0;
        #pragma unroll 4
        for (int kk = 0; kk < 32; kk++) {
            ull a0 = Xd[(r0 + 0) * 33 + kk];
            ull a1 = Xd[(r0 + 1) * 33 + kk];
            ull a2 = Xd[(r0 + 2) * 33 + kk];
            ull a3 = Xd[(r0 + 3) * 33 + kk];
            const ull* wr = Wc + kk * 66 + tx;
            #pragma unroll
            for (int j = 0; j < 4; j++) {
                ull b = wr[16 * j];
                fma2(acc[0][j], a0, b);
                fma2(acc[1][j], a1, b);
                fma2(acc[2][j], a2, b);
                fma2(acc[3][j], a3, b);
            }
        }
        __syncthreads();            // compute done; Xd reusable, W buf consumed
        if (more) {
            #pragma unroll
            for (int u = 0; u < 8; u++)
                Xd[(rb + 8 * u) * 33 + kkx] = packf2(xr[u], xr[u]);
            cp_wait0();             // alternate W buffer landed
        }
        __syncthreads();
        cur ^= 1;
    }

    const int h = n0 >> 7;                 // n-tile spans exactly one head
    #pragma unroll
    for (int j = 0; j < 4; j++) {
        int cp = tx + 16 * j;
        int d  = 2 * cp;
        ull bpair = *(const ull*)(bias + n0 + d);
        #pragma unroll
        for (int i = 0; i < 4; i++) {
            ull* dst = (ull*)(out + (size_t)(h * SEQ + m0 + r0 + i) * DH + d);
            *dst = add2(acc[i][j], bpair);
        }
    }
}

// ---------------- score kernel: 64q x 64k tiles, cp.async K pipeline (R14) ----------------
// sm floats: Qs[64][128] @0 (8192), Ks0[64][130] @8192 (8320), Ks1 @16512 (8320)
//   -> 24832 floats = 99328 B  (2 CTAs/SM)
#define SC_SMEM_BYTES (24832 * 4)

__global__ __launch_bounds__(256, 2) void score_kernel(void)
{
    extern __shared__ __align__(16) float sm[];
    float* Qs  = sm;                 // stride 128 (a-loads broadcast)
    float* Ks0 = sm + 8192;          // stride 130 (b-loads conflict-free)
    float* Ks1 = sm + 16512;

    const int t  = threadIdx.x;
    const int tx = t & 15, ty = t >> 4;
    const int h  = blockIdx.y;
    const int q0 = blockIdx.x << 6;
    const int mc = g_mcount;
    if (q0 >= mc) return;

    const unsigned qb  = (unsigned)__cvta_generic_to_shared(Qs);
    const unsigned kb0 = (unsigned)__cvta_generic_to_shared(Ks0);
    const unsigned kb1 = (unsigned)__cvta_generic_to_shared(Ks1);

    // prologue: Q tile (contiguous 32 KB) + K tile 0 via cp.async
    const float* Qg     = g_Q + (size_t)(h * SEQ + q0) * DH;
    const float* KgBase = g_K + (size_t)(h * SEQ) * DH;
    #pragma unroll
    for (int u = 0; u < 8; u++) {
        int c = t + 256 * u;                 // 16B chunk; layout is plain contiguous
        cp16(qb + (unsigned)c * 16, Qg + c * 4);
    }
    #pragma unroll
    for (int u = 0; u < 16; u++) {
        int c = t + 256 * u;                 // 8B chunk: row = c>>6, pair c&63
        int r = c >> 6, c2 = c & 63;
        cp8(kb0 + (unsigned)(r * 130 + c2 * 2) * 4, KgBase + c * 2);
    }
    cp_commit();

    float bv_[4]; int bi_[4];
    #pragma unroll
    for (int i = 0; i < 4; i++) { bv_[i] = INFINITY; bi_[i] = 0; }

    cp_wait0();
    __syncthreads();

    const int r0 = ty << 2;
    const int nkt = g_mcount64 >> 6;
    int cur = 0;

    for (int kt = 0; kt < nkt; kt++) {
        // prefetch next K tile into alternate buffer
        if (kt + 1 < nkt) {
            unsigned kb = cur ? kb0 : kb1;
            const float* Kg = KgBase + (size_t)((kt + 1) << 6) * DH;
            #pragma unroll
            for (int u = 0; u < 16; u++) {
                int c = t + 256 * u;
                int r = c >> 6, c2 = c & 63;
                cp8(kb + (unsigned)(r * 130 + c2 * 2) * 4, Kg + c * 2);
            }
            cp_commit();
        }

        const float* Ks = cur ? Ks1 : Ks0;
        const int k0 = kt << 6;

        ull acc[4][4];
        #pragma unroll
        for (int i = 0; i < 4; i++)
            #pragma unroll
            for (int j = 0; j < 4; j++) acc[i][j] = 0ull;

        #pragma unroll 4
        for (int dp = 0; dp < 64; dp++) {
            ull a0 = *(const ull*)&Qs[(r0 + 0) * 128 + 2 * dp];
            ull a1 = *(const ull*)&Qs[(r0 + 1) * 128 + 2 * dp];
            ull a2 = *(const ull*)&Qs[(r0 + 2) * 128 + 2 * dp];
            ull a3 = *(const ull*)&Qs[(r0 + 3) * 128 + 2 * dp];
            #pragma unroll
            for (int j = 0; j < 4; j++) {
                ull b = *(const ull*)&Ks[(tx + 16 * j) * 130 + 2 * dp];
                fma2(acc[0][j], a0, b);
                fma2(acc[1][j], a1, b);
                fma2(acc[2][j], a2, b);
                fma2(acc[3][j], a3, b);
            }
        }
        #pragma unroll
        for (int i = 0; i < 4; i++) {
            #pragma unroll
            for (int j = 0; j < 4; j++) {
                int c = k0 + tx + 16 * j;
                float s = f2sum(acc[i][j]);
                if (c < mc && s < bv_[i]) { bv_[i] = s; bi_[i] = c; }
            }
        }

        cp_wait0();                // next tile landed
        __syncthreads();           // all threads done with consumed buffer
        cur ^= 1;
    }

    // half-warp shuffle argmin (row r0+i owned by 16 lanes with same ty)
    #pragma unroll
    for (int i = 0; i < 4; i++) {
        #pragma unroll
        for (int off = 8; off >= 1; off >>= 1) {
            float ov = __shfl_xor_sync(0xffffffffu, bv_[i], off);
            int   oi = __shfl_xor_sync(0xffffffffu, bi_[i], off);
            if (ov < bv_[i]) { bv_[i] = ov; bi_[i] = oi; }
        }
    }
    if (tx == 0) {
        #pragma unroll
        for (int i = 0; i < 4; i++) {
            int row = q0 + r0 + i;
            if (row < mc) g_kbest[h * SEQ + g_midx[row]] = bi_[i];
        }
    }
}

// ---------------- mean(X) and mean-V via linearity ----------------
__global__ void xpart_kernel(const float* __restrict__ X)
{
    int j  = blockIdx.x * 256 + threadIdx.x;   // grid.x = 4
    int rb = blockIdx.y;                        // 8
    const float* p = X + (size_t)rb * 256 * DM + j;
    float s = 0.0f;
    #pragma unroll 8
    for (int r = 0; r < 256; r++) s += p[(size_t)r * DM];
    g_xpart[rb][j] = s;
}
__global__ void xmean_kernel(void)
{
    int j = blockIdx.x * 256 + threadIdx.x;    // grid 4
    float s = 0.0f;
    #pragma unroll
    for (int rb = 0; rb < 8; rb++) s += g_xpart[rb][j];
    g_xmean[j] = s * (1.0f / 2048.0f);
}
__global__ void vgemv_kernel(const float* __restrict__ Wv)
{
    __shared__ float xm[256];
    int t = threadIdx.x;
    int part = blockIdx.y;                     // 4 k-slices of 256
    xm[t] = g_xmean[part * 256 + t];
    __syncthreads();
    int c = blockIdx.x * 256 + t;              // grid.x 8
    float a0 = 0, a1 = 0, a2 = 0, a3 = 0;
    const float* Wp = Wv + (size_t)part * 256 * HD + c;
    for (int j = 0; j < 256; j += 4) {
        a0 += xm[j + 0] * Wp[(size_t)(j + 0) * HD];
        a1 += xm[j + 1] * Wp[(size_t)(j + 1) * HD];
        a2 += xm[j + 2] * Wp[(size_t)(j + 2) * HD];
        a3 += xm[j + 3] * Wp[(size_t)(j + 3) * HD];
    }
    g_vpart[part][c] = (a0 + a1) + (a2 + a3);
}
__global__ void vcombine_kernel(const float* __restrict__ bv)
{
    int c = blockIdx.x * 256 + threadIdx.x;    // grid 8
    g_vmean[c] = ((g_vpart[0][c] + g_vpart[1][c]) + (g_vpart[2][c] + g_vpart[3][c])) + bv[c];
}

// ---------------- output assembly ----------------
__global__ void assemble_kernel(float* __restrict__ out)
{
    int s = blockIdx.x;
    int t = threadIdx.x;               // 256
    if (g_mask[s]) {
        #pragma unroll
        for (int i = 0; i < 8; i++) {
            int idx = i * 256 + t;
            int h = idx >> 7, d = idx & 127;
            int kb = g_kbest[h * SEQ + s];
            out[(size_t)s * HD + idx] = g_V[(size_t)(h * SEQ + kb) * DH + d];
        }
    } else {
        #pragma unroll
        for (int i = 0; i < 8; i++) {
            int idx = i * 256 + t;
            out[(size_t)s * HD + idx] = g_vmean[idx];
        }
    }
}

// ---------------- launch ----------------
extern "C" void kernel_launch(void* const* d_in, const int* in_sizes, int n_in,
                              void* d_out, int out_size)
{
    const float* X          = (const float*)d_in[0];
    const unsigned char* mp = (const unsigned char*)d_in[1];
    const float* Wq = (const float*)d_in[2];
    const float* bq = (const float*)d_in[3];
    const float* Wk = (const float*)d_in[4];
    const float* bk = (const float*)d_in[5];
    const float* Wv = (const float*)d_in[6];
    const float* bv = (const float*)d_in[7];
    float* out = (float*)d_out;

    mask_setup_kernel<<<1, 1024>>>(mp);

    xpart_kernel<<<dim3(4, 8), 256>>>(X);
    xmean_kernel<<<4, 256>>>();

    cudaFuncSetAttribute(proj_kernel, cudaFuncAttributeMaxDynamicSharedMemorySize, PROJ_SMEM_BYTES);
    proj_kernel<<<dim3(HD / 128, SEQ / 64, 3), 256, PROJ_SMEM_BYTES>>>(X, Wq, bq, Wk, bk, Wv, bv);

    vgemv_kernel<<<dim3(8, 4), 256>>>(Wv);
    vcombine_kernel<<<8, 256>>>(bv);

    cudaFuncSetAttribute(score_kernel, cudaFuncAttributeMaxDynamicSharedMemorySize, SC_SMEM_BYTES);
    score_kernel<<<dim3(SEQ / 64, NH), 256, SC_SMEM_BYTES>>>();

    assemble_kernel<<<SEQ, 256>>>(out);
}